// round 2
// baseline (speedup 1.0000x reference)
#include <cuda_runtime.h>
#include <cuda_fp16.h>
#include <cstdint>

// ---------------- fixed problem sizes ----------------
#define B_   4
#define T_   2048
#define S_   4096
#define D_   512
#define MQ_  (B_*T_)    // 8192
#define MK_  (B_*S_)    // 16384
#define KD   512

// ---------------- GEMM tiling ----------------
#define BM 128
#define BN 128
#define BK 64
#define NCH (KD/BK)             // 8 k-chunks
#define STAGE_BYTES (BM*128 + BN*128)   // 32 KB per stage (A 16K + B 16K)
#define SMEM_BYTES  (2*STAGE_BYTES)     // 64 KB, double buffered

// ---------------- scratch (device globals; no allocation allowed) ----------------
__device__ __half g_xq[MQ_ * KD];
__device__ __half g_xk[MK_ * KD];
__device__ __half g_wq[KD * KD];
__device__ __half g_wk[KD * KD];
__device__ __half g_q [MQ_ * KD];
__device__ __half g_k [MK_ * KD];

// ---------------- helpers ----------------
#define SWZ(o) ((o) ^ (((o) >> 3) & 0x70))   // SW128: XOR bits[6:4] ^= bits[9:7]

__device__ __forceinline__ uint32_t smem_u32(const void* p) {
    uint32_t a;
    asm("{ .reg .u64 t; cvta.to.shared.u64 t, %1; cvt.u32.u64 %0, t; }"
        : "=r"(a) : "l"(p));
    return a;
}

__device__ __forceinline__ void cp16(uint32_t s, const void* g) {
    asm volatile("cp.async.cg.shared.global [%0], [%1], 16;" :: "r"(s), "l"(g));
}
#define CP_COMMIT() asm volatile("cp.async.commit_group;" ::: "memory")
#define CP_WAIT0()  asm volatile("cp.async.wait_group 0;" ::: "memory")
#define CP_WAIT1()  asm volatile("cp.async.wait_group 1;" ::: "memory")

__device__ __forceinline__ void ldsm4(uint32_t* r, uint32_t addr) {
    asm volatile("ldmatrix.sync.aligned.m8n8.x4.shared.b16 {%0,%1,%2,%3}, [%4];"
                 : "=r"(r[0]), "=r"(r[1]), "=r"(r[2]), "=r"(r[3]) : "r"(addr));
}

__device__ __forceinline__ void mma16816(float* c, const uint32_t* a,
                                         uint32_t b0, uint32_t b1) {
    asm volatile(
        "mma.sync.aligned.m16n8k16.row.col.f32.f16.f16.f32 "
        "{%0,%1,%2,%3}, {%4,%5,%6,%7}, {%8,%9}, {%0,%1,%2,%3};"
        : "+f"(c[0]), "+f"(c[1]), "+f"(c[2]), "+f"(c[3])
        : "r"(a[0]), "r"(a[1]), "r"(a[2]), "r"(a[3]), "r"(b0), "r"(b1));
}

// ---------------- fp32 -> fp16 convert ----------------
__global__ void f2h_kernel(const float4* __restrict__ x,
                           __half2* __restrict__ o, int n4) {
    int i = blockIdx.x * blockDim.x + threadIdx.x;
    if (i >= n4) return;
    float4 v = x[i];
    o[i * 2 + 0] = __floats2half2_rn(v.x, v.y);
    o[i * 2 + 1] = __floats2half2_rn(v.z, v.w);
}

// ---------------- fp16 GEMM:  D[m,n] = sum_k A[m,k] * B[n,k]  ----------------
// MODE 0 (PROJ):   out = D + bias[n], fp16 store
// MODE 1 (LOGITS): out = D * (1/64), mask[b,n] -> -inf, fp32 store
template <int MODE>
__global__ __launch_bounds__(256, 2) void hgemm(
    const __half* __restrict__ A, const __half* __restrict__ Bm,
    const float* __restrict__ bias, const unsigned char* __restrict__ mask,
    float* __restrict__ outF, __half* __restrict__ outH,
    int aRows, int bRows, int outLd) {
    extern __shared__ char smem[];
    const uint32_t sb = smem_u32(smem);
    const int tid = threadIdx.x;
    const int wid = tid >> 5;
    const int l = tid & 31;
    const int wm = wid >> 2;      // 0..1 : 64-row slab
    const int wn = wid & 3;       // 0..3 : 32-col slab
    const int mt = blockIdx.x, nt = blockIdx.y, bz = blockIdx.z;

    const size_t aBase = ((size_t)bz * aRows + (size_t)mt * BM) * KD;
    const size_t bBase = ((size_t)bz * bRows + (size_t)nt * BN) * KD;

    float acc[4][4][4];
#pragma unroll
    for (int i = 0; i < 4; ++i)
#pragma unroll
        for (int j = 0; j < 4; ++j)
#pragma unroll
            for (int c = 0; c < 4; ++c) acc[i][j][c] = 0.f;

    // per-lane ldmatrix address components
    const int aRow = wm * 64 + (l & 15);
    const int aKsel = ((l >> 4) & 1) * 16;                 // bytes
    const int bRow = wn * 32 + (l & 7) + ((l >> 4) & 1) * 8;
    const int bKsel = ((l >> 3) & 1) * 16;                 // bytes

    auto load_tile = [&](int stg, int k0) {
        const uint32_t sA = sb + stg * STAGE_BYTES;
        const uint32_t sB = sA + BM * 128;
#pragma unroll
        for (int t = 0; t < 4; ++t) {
            int i = tid + t * 256;
            int r = i >> 3, c = i & 7;
            cp16(sA + SWZ((uint32_t)(r * 128 + c * 16)),
                 A + aBase + (size_t)r * KD + k0 + c * 8);
        }
#pragma unroll
        for (int t = 0; t < 4; ++t) {
            int i = tid + t * 256;
            int r = i >> 3, c = i & 7;
            cp16(sB + SWZ((uint32_t)(r * 128 + c * 16)),
                 Bm + bBase + (size_t)r * KD + k0 + c * 8);
        }
    };

    load_tile(0, 0);
    CP_COMMIT();

    int stg = 0;
    for (int ch = 0; ch < NCH; ++ch) {
        if (ch + 1 < NCH) {
            load_tile(stg ^ 1, (ch + 1) * BK);
            CP_COMMIT();
            CP_WAIT1();   // current stage's group done; newest may be in flight
        } else {
            CP_WAIT0();
        }
        __syncthreads();

        const uint32_t sA = sb + stg * STAGE_BYTES;
        const uint32_t sB = sA + BM * 128;
#pragma unroll
        for (int ks = 0; ks < BK / 16; ++ks) {
            uint32_t afr[4][4];
            uint32_t bfr[2][4];
#pragma unroll
            for (int mi = 0; mi < 4; ++mi)
                ldsm4(afr[mi], sA + SWZ((uint32_t)((aRow + mi * 16) * 128 +
                                                   ks * 32 + aKsel)));
#pragma unroll
            for (int nb = 0; nb < 2; ++nb)
                ldsm4(bfr[nb], sB + SWZ((uint32_t)((bRow + nb * 16) * 128 +
                                                   ks * 32 + bKsel)));
#pragma unroll
            for (int mi = 0; mi < 4; ++mi)
#pragma unroll
                for (int ni = 0; ni < 4; ++ni)
                    mma16816(acc[mi][ni], afr[mi], bfr[ni >> 1][(ni & 1) * 2],
                             bfr[ni >> 1][(ni & 1) * 2 + 1]);
        }
        __syncthreads();
        stg ^= 1;
    }

    // ---------------- epilogue ----------------
    const int gid = l >> 2, tig = l & 3;
#pragma unroll
    for (int mi = 0; mi < 4; ++mi) {
#pragma unroll
        for (int ni = 0; ni < 4; ++ni) {
            const int col = nt * BN + wn * 32 + ni * 8 + tig * 2;
#pragma unroll
            for (int half_ : {0, 1}) {
                const int row = mt * BM + wm * 64 + mi * 16 + gid + half_ * 8;
                const float v0 = acc[mi][ni][half_ * 2 + 0];
                const float v1 = acc[mi][ni][half_ * 2 + 1];
                const size_t rowg = (size_t)bz * aRows + row;
                if (MODE == 0) {
                    float o0 = v0 + bias[col];
                    float o1 = v1 + bias[col + 1];
                    *(__half2*)(outH + rowg * outLd + col) =
                        __floats2half2_rn(o0, o1);
                } else {
                    const unsigned char* mrow = mask + (size_t)bz * bRows;
                    const float NEG_INF = __int_as_float(0xff800000);
                    float2 o;
                    o.x = mrow[col + 0] ? NEG_INF : v0 * 0.015625f;
                    o.y = mrow[col + 1] ? NEG_INF : v1 * 0.015625f;
                    *(float2*)(outF + rowg * outLd + col) = o;
                }
            }
        }
    }
}

// ---------------- host launch ----------------
extern "C" void kernel_launch(void* const* d_in, const int* in_sizes, int n_in,
                              void* d_out, int out_size) {
    const float* query = (const float*)d_in[0];
    const float* keys = (const float*)d_in[1];
    const unsigned char* mask = (const unsigned char*)d_in[2];
    const float* q_w = (const float*)d_in[3];
    const float* q_b = (const float*)d_in[4];
    const float* k_w = (const float*)d_in[5];
    const float* k_b = (const float*)d_in[6];

    void *xq, *xk, *wq, *wk, *q, *k;
    cudaGetSymbolAddress(&xq, g_xq);
    cudaGetSymbolAddress(&xk, g_xk);
    cudaGetSymbolAddress(&wq, g_wq);
    cudaGetSymbolAddress(&wk, g_wk);
    cudaGetSymbolAddress(&q, g_q);
    cudaGetSymbolAddress(&k, g_k);

    cudaFuncSetAttribute(hgemm<0>, cudaFuncAttributeMaxDynamicSharedMemorySize,
                         SMEM_BYTES);
    cudaFuncSetAttribute(hgemm<1>, cudaFuncAttributeMaxDynamicSharedMemorySize,
                         SMEM_BYTES);

    // 1) fp32 -> fp16 converts
    {
        int n4 = MQ_ * KD / 4;
        f2h_kernel<<<(n4 + 255) / 256, 256>>>((const float4*)query,
                                              (__half2*)xq, n4);
        n4 = MK_ * KD / 4;
        f2h_kernel<<<(n4 + 255) / 256, 256>>>((const float4*)keys,
                                              (__half2*)xk, n4);
        n4 = KD * KD / 4;
        f2h_kernel<<<(n4 + 255) / 256, 256>>>((const float4*)q_w,
                                              (__half2*)wq, n4);
        f2h_kernel<<<(n4 + 255) / 256, 256>>>((const float4*)k_w,
                                              (__half2*)wk, n4);
    }

    // 2) Q = query @ q_w^T + q_b     [8192, 512] (fp16)
    hgemm<0><<<dim3(MQ_ / BM, KD / BN, 1), 256, SMEM_BYTES>>>(
        (const __half*)xq, (const __half*)wq, q_b, nullptr, nullptr,
        (__half*)q, MQ_, KD, KD);

    // 3) K = keys @ k_w^T + k_b      [16384, 512] (fp16)
    hgemm<0><<<dim3(MK_ / BM, KD / BN, 1), 256, SMEM_BYTES>>>(
        (const __half*)xk, (const __half*)wk, k_b, nullptr, nullptr,
        (__half*)k, MK_, KD, KD);

    // 4) logits = (Q K^T) / 64, masked    [4, 2048, 4096] fp32
    hgemm<1><<<dim3(T_ / BM, S_ / BN, B_), 256, SMEM_BYTES>>>(
        (const __half*)q, (const __half*)k, nullptr, mask, (float*)d_out,
        nullptr, T_, S_, S_);
}